// round 17
// baseline (speedup 1.0000x reference)
#include <cuda_runtime.h>
#include <math.h>

#define T_STEPS 4096
#define BATCH   128
#define IN_DIM  96
#define H_DIM   64
#define OUT_DIM 2

#define CHUNK   32
#define NCHUNK  (T_STEPS / CHUNK)   // 128 (readout chunking)

#define TCH     64                  // producer/scan sync chunk (timesteps)
#define NTCH    (T_STEPS / TCH)     // 64
#define NCTA    128
#define NB      4                   // batches multiplexed per scan warp
#define NSCAN   (BATCH / NB)        // 32 scan CTAs

typedef unsigned long long ull;

// Scratch (padded by 8 timesteps so prefetches need no bounds branch)
__device__ float g_P[(size_t)(T_STEPS + 8) * BATCH * H_DIM];
__device__ ull   g_M[(size_t)(T_STEPS + 8) * BATCH];
__device__ ulonglong2 g_S[NCHUNK * BATCH];
__device__ ulonglong2 g_Pref[NCHUNK * BATCH];
__device__ float2 g_tab[CHUNK];
__device__ int    g_done[NTCH];      // producer progress (counts to NCTA)
__device__ int    g_scandone[NTCH];  // scan progress (counts to NSCAN)

// ---------- packed f32x2 helpers ----------
__device__ __forceinline__ void fma2(ull& d, ull a, ull b) {
    asm("fma.rn.f32x2 %0, %1, %2, %0;" : "+l"(d) : "l"(a), "l"(b));
}
__device__ __forceinline__ ull fma2g(ull a, ull b, ull c) {
    ull d;
    asm("fma.rn.f32x2 %0, %1, %2, %3;" : "=l"(d) : "l"(a), "l"(b), "l"(c));
    return d;
}
__device__ __forceinline__ ull add2(ull a, ull b) {
    ull d;
    asm("add.rn.f32x2 %0, %1, %2;" : "=l"(d) : "l"(a), "l"(b));
    return d;
}
__device__ __forceinline__ ull mul2(ull a, ull b) {
    ull d;
    asm("mul.rn.f32x2 %0, %1, %2;" : "=l"(d) : "l"(a), "l"(b));
    return d;
}
__device__ __forceinline__ ull pack2(float x, float y) {
    ull r;
    asm("mov.b64 %0, {%1, %2};" : "=l"(r) : "f"(x), "f"(y));
    return r;
}
__device__ __forceinline__ float lo32(ull v) { return __uint_as_float((unsigned)v); }
__device__ __forceinline__ float hi32(ull v) { return __uint_as_float((unsigned)(v >> 32)); }

__device__ __forceinline__ unsigned smem_u32(const void* p) {
    unsigned a;
    asm("{ .reg .u64 t; cvta.to.shared.u64 t, %1; cvt.u32.u64 %0, t; }" : "=r"(a) : "l"(p));
    return a;
}
__device__ __forceinline__ ull lds_u64(unsigned a) {
    ull v;
    asm("ld.shared.b64 %0, [%1];" : "=l"(v) : "r"(a));
    return v;
}
__device__ __forceinline__ void stg_pred(unsigned cond, ull* addr, ull v) {
    asm volatile(
        "{\n\t.reg .pred p;\n\tsetp.ne.u32 p, %0, 0;\n\t@p st.global.b64 [%1], %2;\n\t}"
        :: "r"(cond), "l"(addr), "l"(v));
}
__device__ __forceinline__ void release_inc(int* p) {
    asm volatile("red.release.gpu.global.add.s32 [%0], 1;" :: "l"(p) : "memory");
}
__device__ __forceinline__ int acquire_ld(const int* p) {
    int v;
    asm volatile("ld.acquire.gpu.global.s32 %0, [%1];" : "=r"(v) : "l"(p) : "memory");
    return v;
}

// ============================================================
// Kernel 0: reset progress counters (graph-replay safe)
// ============================================================
__global__ void zero_done() {
    if (threadIdx.x < NTCH)          g_done[threadIdx.x] = 0;
    else if (threadIdx.x < 2 * NTCH) g_scandone[threadIdx.x - NTCH] = 0;
}

// ============================================================
// HYBRID kernel: 128 CTAs x 128 threads, ONE CTA PER SM.
//  warps 0,1 (SMSP0/1): input-GEMM producer for all 64 chunks,
//    then readout chunk `bid` when the scan fleet has published it.
//  warp 3   (SMSP3, CTAs 0..31 only): serial scans for FOUR
//    batches 4*bid..4*bid+3, interleaved per step so the four
//    dependency chains hide each other's latency.
//  warp 2: idle.
// ============================================================
__global__ __launch_bounds__(128, 1) void hybrid_kernel(const float* __restrict__ x,
                                                        const float* __restrict__ Wh,
                                                        const float* __restrict__ V,
                                                        const float* __restrict__ Wo,
                                                        float* __restrict__ out,
                                                        float a_h, float b_h) {
    extern __shared__ __align__(16) char dsm[];   // scan LUT region
    __shared__ ull xp[48][64];                    // 24 KB producer x tile
    __shared__ ull wp[48][64];                    // 24 KB producer W tile
    __shared__ float2 lutOb[8 * 256];             // 16 KB readout byte-LUT

    const int tid  = threadIdx.x;
    const int bid  = blockIdx.x;

    if (tid < 64) {
        // ================= PRODUCER (warps 0,1) =================
        const int fr = tid >> 3;
        const int fq = tid & 7;

        for (int idx = tid; idx < 8 * 256; idx += 64) {
            int pp = idx >> 8, v = idx & 255;
            float2 s = make_float2(0.f, 0.f);
#pragma unroll
            for (int i = 0; i < 8; i++) {
                if (v & (1 << i)) {
                    int j = (pp < 4) ? 2 * (8 * pp + i) : 2 * (8 * (pp - 4) + i) + 1;
                    s.x += Wo[j];
                    s.y += Wo[H_DIM + j];
                }
            }
            lutOb[idx] = s;
        }

#pragma unroll
        for (int rr = 0; rr < 8; rr++) {
            int c = rr * 8 + fr;
            const float4* src = (const float4*)(Wh + (size_t)c * IN_DIM) + fq * 3;
#pragma unroll
            for (int j = 0; j < 3; j++) {
                float4 f = src[j];
                int kk = (fq * 3 + j) * 2;
                *(float2*)&wp[kk][c]     = make_float2(f.x, f.y);
                *(float2*)&wp[kk + 1][c] = make_float2(f.z, f.w);
            }
        }

        const int r0 = (tid & 7) * 8;
        const int c0 = (tid >> 3) * 8;

        for (int c = 0; c < NTCH; c++) {
            const long long row0 = ((long long)c * NCTA + bid) * 64;

#pragma unroll
            for (int rr = 0; rr < 8; rr++) {
                int r = rr * 8 + fr;
                long long g = row0 + r;
#pragma unroll
                for (int j = 0; j < 3; j++) {
                    float4 f = make_float4(0.f, 0.f, 0.f, 0.f);
                    if (g >= BATCH)
                        f = ((const float4*)(x + (g - BATCH) * IN_DIM))[fq * 3 + j];
                    int kk = (fq * 3 + j) * 2;
                    *(float2*)&xp[kk][r]     = make_float2(f.x, f.y);
                    *(float2*)&xp[kk + 1][r] = make_float2(f.z, f.w);
                }
            }
            asm volatile("bar.sync 1, 64;" ::: "memory");

            ull acc[8][8];
#pragma unroll
            for (int i = 0; i < 8; i++)
#pragma unroll
                for (int j = 0; j < 8; j++) acc[i][j] = 0ull;

#pragma unroll 2
            for (int kk = 0; kk < 48; kk++) {
                ulonglong2 A[4], B[4];
#pragma unroll
                for (int j = 0; j < 4; j++) {
                    A[j] = *(const ulonglong2*)&xp[kk][r0 + 2 * j];
                    B[j] = *(const ulonglong2*)&wp[kk][c0 + 2 * j];
                }
#pragma unroll
                for (int ri = 0; ri < 8; ri++) {
                    ull av = (ri & 1) ? A[ri >> 1].y : A[ri >> 1].x;
#pragma unroll
                    for (int cj = 0; cj < 4; cj++) {
                        fma2(acc[ri][2 * cj],     av, B[cj].x);
                        fma2(acc[ri][2 * cj + 1], av, B[cj].y);
                    }
                }
            }

#pragma unroll
            for (int ri = 0; ri < 8; ri++) {
                float4 o0, o1;
                o0.x = lo32(acc[ri][0]) + hi32(acc[ri][0]);
                o0.y = lo32(acc[ri][1]) + hi32(acc[ri][1]);
                o0.z = lo32(acc[ri][2]) + hi32(acc[ri][2]);
                o0.w = lo32(acc[ri][3]) + hi32(acc[ri][3]);
                o1.x = lo32(acc[ri][4]) + hi32(acc[ri][4]);
                o1.y = lo32(acc[ri][5]) + hi32(acc[ri][5]);
                o1.z = lo32(acc[ri][6]) + hi32(acc[ri][6]);
                o1.w = lo32(acc[ri][7]) + hi32(acc[ri][7]);
                float* dst = g_P + (size_t)(row0 + r0 + ri) * H_DIM + c0;
                *(float4*)dst       = o0;
                *(float4*)(dst + 4) = o1;
            }

            __threadfence();
            asm volatile("bar.sync 1, 64;" ::: "memory");
            if (tid == 0) release_inc(&g_done[c]);
        }

        // ================= READOUT (chunk = bid) =================
        {
            const int cc = bid;
            const int need64 = (cc * CHUNK + CHUNK - 1) >> 6;
            if (tid == 0)
                while (acquire_ld(&g_scandone[need64]) < NSCAN) {}
            asm volatile("bar.sync 1, 64;" ::: "memory");

            const ull a_o2  = pack2(a_h, a_h);
            const ull b_o2  = pack2(b_h, b_h);
            const ull ombo2 = pack2(1.f - b_h, 1.f - b_h);

#pragma unroll
            for (int half = 0; half < 2; half++) {
                const int b = tid + half * 64;

                ull syno2 = 0ull, memo2 = 0ull;
                const ull* mp = g_M + ((long long)cc * CHUNK - 1) * BATCH + b;
                ull ring[8];
#pragma unroll
                for (int q = 0; q < 8; q++)
                    ring[q] = (cc == 0 && q == 0) ? 0ull : mp[(size_t)q * BATCH];
                const ull* pfm = mp + (size_t)8 * BATCH;

                ull* optr = (ull*)out + (size_t)cc * CHUNK * BATCH + b;

                for (int jb = 0; jb < CHUNK; jb += 8) {
#pragma unroll
                    for (int q8 = 0; q8 < 8; q8++) {
                        const int j = jb + q8;
                        ull m = ring[q8];
                        ring[q8] = *pfm;
                        pfm += BATCH;

                        unsigned p0 = (unsigned)m, p1 = (unsigned)(m >> 32);
                        ull r0_ = add2(*(const ull*)&lutOb[0 * 256 + (p0 & 255u)],
                                       *(const ull*)&lutOb[4 * 256 + (p1 & 255u)]);
                        ull r1_ = add2(*(const ull*)&lutOb[1 * 256 + ((p0 >> 8) & 255u)],
                                       *(const ull*)&lutOb[5 * 256 + ((p1 >> 8) & 255u)]);
                        ull r2_ = add2(*(const ull*)&lutOb[2 * 256 + ((p0 >> 16) & 255u)],
                                       *(const ull*)&lutOb[6 * 256 + ((p1 >> 16) & 255u)]);
                        ull r3_ = add2(*(const ull*)&lutOb[3 * 256 + (p0 >> 24)],
                                       *(const ull*)&lutOb[7 * 256 + (p1 >> 24)]);
                        ull d2 = add2(add2(r0_, r1_), add2(r2_, r3_));

                        syno2 = fma2g(a_o2, syno2, d2);
                        memo2 = fma2g(b_o2, memo2, mul2(ombo2, syno2));
                        optr[(size_t)j * BATCH] = memo2;
                    }
                }
                g_S[cc * BATCH + b] = make_ulonglong2(syno2, memo2);
            }
        }
        return;
    }

    // ================= SCAN (warp 3, CTAs 0..31, 4 batches each) =================
    if (tid < 96 || bid >= NSCAN) return;
    const int lane = tid - 96;
    const int b0   = bid * NB;

    const unsigned raw32 = smem_u32(dsm);
    const unsigned abase = (raw32 + 8191u) & ~8191u;
    char* ab = dsm + (abase - raw32);

    // ---- build LUT: 13 positions x 32 entries x 32 lanes x float2 ----
    for (int p = 0; p < 13; p++) {
        char* bpp = ab + p * 8192 + lane * 8;
        *(float2*)bpp = make_float2(0.f, 0.f);
#pragma unroll
        for (int i = 0; i < 5; i++) {
            int n = 5 * p + i;
            float2 c = make_float2(0.f, 0.f);
            if (n < 64) {
                int j = (n < 32) ? 2 * n : 2 * (n - 32) + 1;
                c.x = V[(size_t)(2 * lane) * H_DIM + j];
                c.y = V[(size_t)(2 * lane + 1) * H_DIM + j];
            }
            *(float2*)(bpp + (1u << i) * 256) = c;
        }
        for (int v = 3; v < 32; v++) {
            if ((v & (v - 1)) == 0) continue;
            float2 e1 = *(const float2*)(bpp + (v & (v - 1)) * 256);
            float2 e2 = *(const float2*)(bpp + (v & (-v)) * 256);
            *(float2*)(bpp + v * 256) = make_float2(e1.x + e2.x, e1.y + e2.y);
        }
    }
    __syncwarp();

    unsigned bp[13];
#pragma unroll
    for (int p = 0; p < 13; p++) bp[p] = abase + p * 8192 + lane * 8;

    const float omb_h = 1.f - b_h;
    const ull a_h2 = pack2(a_h, a_h);
    const ull omb2 = pack2(omb_h, omb_h);
    const ull b_h2 = pack2(b_h, b_h);

    ull syn2[NB], mem2[NB];
    unsigned pm0[NB], pm1[NB];
#pragma unroll
    for (int n = 0; n < NB; n++) {
        syn2[n] = 0ull; mem2[n] = 0ull; pm0[n] = 0u; pm1[n] = 0u;
    }

    while (acquire_ld(&g_done[0]) < NCTA) {}

    const int strideP = BATCH * H_DIM;
    const float* p = g_P + (size_t)b0 * H_DIM + 2 * lane;
    float2 cur[NB][8];
#pragma unroll
    for (int n = 0; n < NB; n++)
#pragma unroll
        for (int q = 0; q < 8; q++)
            cur[n][q] = *(const float2*)(p + n * H_DIM + (size_t)q * strideP);
    const float* pf = p + (size_t)8 * strideP;

    ull* mptr = g_M + b0;
    const unsigned M5 = 0x1F00u;
    const unsigned is0 = (lane == 0) ? 1u : 0u;

    for (int tb = 0; tb < T_STEPS; tb += 8) {
        if ((tb & (TCH - 1)) == 0) {
            const int cw = tb / TCH;
            const int need = (cw + 1 < NTCH) ? cw + 1 : NTCH - 1;
            while (acquire_ld(&g_done[need]) < NCTA) {}
            if (is0 && cw > 0) release_inc(&g_scandone[cw - 1]);
        }
#pragma unroll
        for (int q8 = 0; q8 < 8; q8++) {
#pragma unroll
            for (int n = 0; n < NB; n++) {
                const unsigned m0_ = pm0[n], m1_ = pm1[n];
                ull h0 = lds_u64(((m0_ << 8)  & M5) | bp[0]);
                ull h1 = lds_u64(((m0_ << 3)  & M5) | bp[1]);
                ull h2 = lds_u64(((m0_ >> 2)  & M5) | bp[2]);
                ull h3 = lds_u64(((m0_ >> 7)  & M5) | bp[3]);
                ull h4 = lds_u64(((m0_ >> 12) & M5) | bp[4]);
                ull h5 = lds_u64(((m0_ >> 17) & M5) | bp[5]);
                ull h6 = lds_u64((__funnelshift_r(m0_, m1_, 22) & M5) | bp[6]);
                ull h7 = lds_u64(((m1_ << 5)  & M5) | bp[7]);
                ull h8 = lds_u64((m1_         & M5) | bp[8]);
                ull h9 = lds_u64(((m1_ >> 5)  & M5) | bp[9]);
                ull hA = lds_u64(((m1_ >> 10) & M5) | bp[10]);
                ull hB = lds_u64(((m1_ >> 15) & M5) | bp[11]);
                ull hC = lds_u64(((m1_ >> 20) & M5) | bp[12]);

                float2 c = cur[n][q8];
                cur[n][q8] = *(const float2*)(pf + n * H_DIM);

                ull s0 = add2(h0, h1);
                ull s1 = add2(h2, h3);
                ull s2 = add2(h4, h5);
                ull s3 = add2(h6, h7);
                ull s4 = add2(h8, h9);
                ull s5 = add2(hA, hB);
                ull s6 = add2(hC, pack2(c.x, c.y));
                ull t0 = add2(s0, s1);
                ull t1 = add2(s2, s3);
                ull t2 = add2(s4, s5);
                ull tot = add2(add2(t0, t1), add2(t2, s6));

                syn2[n] = fma2g(a_h2, syn2[n], tot);
                mem2[n] = fma2g(b_h2, mem2[n], mul2(omb2, syn2[n]));
                float m0f = lo32(mem2[n]), m1f = hi32(mem2[n]);
                bool sp0 = (m0f > 1.f);
                bool sp1 = (m1f > 1.f);
                m0f = sp0 ? 0.f : m0f;
                m1f = sp1 ? 0.f : m1f;
                mem2[n] = pack2(m0f, m1f);
                pm0[n] = __ballot_sync(0xffffffffu, sp0);
                pm1[n] = __ballot_sync(0xffffffffu, sp1);

                stg_pred(is0, mptr + n, (ull)pm0[n] | ((ull)pm1[n] << 32));
            }
            pf += strideP;
            mptr += BATCH;
        }
    }
    if (is0) release_inc(&g_scandone[NTCH - 1]);
}

// ============================================================
// Kernel 4: chunk prefix (NCHUNK=128, 16-deep block prefetch).
// ============================================================
__global__ __launch_bounds__(128) void readout_prefix(float a_o, float b_o) {
    const int b = threadIdx.x;

    float ap = a_o, bpw = b_o, g = (1.f - b_o) * a_o;
    float aC = 0.f, bC = 0.f, gC = 0.f;
    for (int j = 0; j < CHUNK; j++) {
        if (b == 0) g_tab[j] = make_float2(bpw, g);
        if (j == CHUNK - 1) { aC = ap; bC = bpw; gC = g; }
        ap *= a_o;
        bpw *= b_o;
        g = b_o * g + (1.f - b_o) * ap;
    }

    const ull aC2 = pack2(aC, aC);
    const ull bC2 = pack2(bC, bC);
    const ull gC2 = pack2(gC, gC);

    ulonglong2 buf[2][16];
#pragma unroll
    for (int q = 0; q < 16; q++) buf[0][q] = g_S[q * BATCH + b];

    ull S = 0ull, M = 0ull;
#pragma unroll
    for (int blk = 0; blk < NCHUNK / 16; blk++) {
        if (blk < NCHUNK / 16 - 1) {
#pragma unroll
            for (int q = 0; q < 16; q++)
                buf[(blk + 1) & 1][q] = g_S[((blk + 1) * 16 + q) * BATCH + b];
        }
#pragma unroll
        for (int q = 0; q < 16; q++) {
            int c = blk * 16 + q;
            g_Pref[c * BATCH + b] = make_ulonglong2(S, M);
            ulonglong2 sm = buf[blk & 1][q];
            ull Sold = S;
            S = fma2g(aC2, S, sm.x);
            M = add2(fma2g(bC2, M, sm.y), mul2(gC2, Sold));
        }
    }
}

// ============================================================
// Kernel 5: fixup: out[t][b] += b^{j+1}*M_c + g_j*S_c
// ============================================================
__global__ __launch_bounds__(256) void readout_fix(float* __restrict__ out) {
    const size_t idx = (size_t)blockIdx.x * 256 + threadIdx.x;
    const int t = (int)(idx >> 7);
    const int b = (int)(idx & 127);
    const int c = t / CHUNK;
    const int j = t % CHUNK;

    float2 tab = g_tab[j];
    ulonglong2 pref = g_Pref[c * BATCH + b];
    ull fix = add2(mul2(pack2(tab.x, tab.x), pref.y),
                   mul2(pack2(tab.y, tab.y), pref.x));
    ull* o = (ull*)out + idx;
    *o = add2(*o, fix);
}

// ============================================================
extern "C" void kernel_launch(void* const* d_in, const int* in_sizes, int n_in,
                              void* d_out, int out_size) {
    const float* x  = (const float*)d_in[0];
    const float* Wh = (const float*)d_in[1];
    const float* V  = (const float*)d_in[2];
    const float* Wo = (const float*)d_in[3];
    float* out = (float*)d_out;

    const double S = log1p(exp(1.0));
    const float a_h = expf((float)(-0.004 / (S * 0.01)));
    const float b_h = expf((float)(-0.004 / (S * 0.02)));

    const int smem_dyn = 13 * 8192 + 8192;   // 112 KB dynamic (scan LUT + align pad)
    cudaFuncSetAttribute(hybrid_kernel, cudaFuncAttributeMaxDynamicSharedMemorySize,
                         smem_dyn);
    cudaFuncSetAttribute(hybrid_kernel, cudaFuncAttributePreferredSharedMemoryCarveout,
                         100);

    zero_done<<<1, 128>>>();
    hybrid_kernel<<<NCTA, 128, smem_dyn>>>(x, Wh, V, Wo, out, a_h, b_h);
    readout_prefix<<<1, 128>>>(a_h, b_h);
    readout_fix<<<(T_STEPS * BATCH) / 256, 256>>>(out);
}